// round 9
// baseline (speedup 1.0000x reference)
#include <cuda_runtime.h>
#include <math.h>

#define DTF 1e-4f
#define LN_EPS 1e-5f

constexpr int Bb = 16;    // batch
constexpr int S  = 4096;  // sequence
constexpr int D  = 256;   // model dim
constexpr int N  = 16;    // state dim
constexpr int L  = 128;   // chunk length
constexpr int NC = S / L; // 32 chunks per batch

__device__ float g_p[Bb * S * N];        // local prefix states (4 MB)
__device__ float g_carry[Bb * NC * N];   // per-chunk carries

typedef unsigned long long ull;

__device__ __forceinline__ void fma2(ull& d, ull a, ull b) {
    asm("fma.rn.f32x2 %0, %1, %2, %0;" : "+l"(d) : "l"(a), "l"(b));
}
__device__ __forceinline__ ull fma2g(ull a, ull b, ull c) {
    ull d; asm("fma.rn.f32x2 %0, %1, %2, %3;" : "=l"(d) : "l"(a), "l"(b), "l"(c)); return d;
}
__device__ __forceinline__ ull mul2(ull a, ull b) {
    ull d; asm("mul.rn.f32x2 %0, %1, %2;" : "=l"(d) : "l"(a), "l"(b)); return d;
}
__device__ __forceinline__ ull add2(ull a, ull b) {
    ull d; asm("add.rn.f32x2 %0, %1, %2;" : "=l"(d) : "l"(a), "l"(b)); return d;
}
__device__ __forceinline__ ull splat2(float v) {
    ull r; asm("mov.b64 %0, {%1, %1};" : "=l"(r) : "f"(v)); return r;
}
__device__ __forceinline__ float fold2(ull v) {
    float lo, hi; asm("mov.b64 {%0, %1}, %2;" : "=f"(lo), "=f"(hi) : "l"(v));
    return lo + hi;
}

__device__ __forceinline__ float clip10(float v) {
    return fminf(fmaxf(v, -10.0f), 10.0f);
}

// 32-value butterfly reduction: lane l ends with the full 32-lane sum of v[l].
__device__ __forceinline__ float mv_reduce32(float v[32], int lane) {
    {
        const bool hb = (lane & 16) != 0;
        #pragma unroll
        for (int t = 0; t < 16; t++) {
            float keep = hb ? v[t + 16] : v[t];
            float send = hb ? v[t] : v[t + 16];
            v[t] = keep + __shfl_xor_sync(0xffffffffu, send, 16);
        }
    }
    {
        const bool hb = (lane & 8) != 0;
        #pragma unroll
        for (int t = 0; t < 8; t++) {
            float keep = hb ? v[t + 8] : v[t];
            float send = hb ? v[t] : v[t + 8];
            v[t] = keep + __shfl_xor_sync(0xffffffffu, send, 8);
        }
    }
    {
        const bool hb = (lane & 4) != 0;
        #pragma unroll
        for (int t = 0; t < 4; t++) {
            float keep = hb ? v[t + 4] : v[t];
            float send = hb ? v[t] : v[t + 4];
            v[t] = keep + __shfl_xor_sync(0xffffffffu, send, 4);
        }
    }
    {
        const bool hb = (lane & 2) != 0;
        #pragma unroll
        for (int t = 0; t < 2; t++) {
            float keep = hb ? v[t + 2] : v[t];
            float send = hb ? v[t] : v[t + 2];
            v[t] = keep + __shfl_xor_sync(0xffffffffu, send, 2);
        }
    }
    {
        const bool hb = (lane & 1) != 0;
        float keep = hb ? v[1] : v[0];
        float send = hb ? v[0] : v[1];
        v[0] = keep + __shfl_xor_sync(0xffffffffu, send, 1);
    }
    return v[0];
}

// ---------------------------------------------------------------------------
// Kernel A (unchanged): warp-split GEMM + 2-level local scan.
// ---------------------------------------------------------------------------
__global__ void __launch_bounds__(256, 2) kA(const float* __restrict__ x,
                                             const float* __restrict__ A,
                                             const float* __restrict__ Bm) {
    __shared__ float bd[N * D];        // bd[n*256+d] = DT*Bm[n][d]
    __shared__ float Wbuf[L * N];
    __shared__ float sub[8 * N], pre[8 * N];

    const int c = blockIdx.x, b = blockIdx.y;
    const int tid = threadIdx.x, lane = tid & 31, warp = tid >> 5;
    const int rg = warp >> 1, nh = warp & 1;

    {
        const float4* Bm4 = reinterpret_cast<const float4*>(Bm);
        float4* bd4 = reinterpret_cast<float4*>(bd);
        for (int idx = tid; idx < N * D / 4; idx += 256) {
            float4 v = Bm4[idx];
            v.x *= DTF; v.y *= DTF; v.z *= DTF; v.w *= DTF;
            bd4[idx] = v;
        }
    }
    __syncthreads();

    const ulonglong2* xw = reinterpret_cast<const ulonglong2*>(
        x + (size_t)(b * S + c * L + rg * 32) * D);
    const ulonglong2* bdu = reinterpret_cast<const ulonglong2*>(bd);

    #pragma unroll 1
    for (int q = 0; q < 8; q++) {
        ulonglong2 xv[4][2];
        #pragma unroll
        for (int r = 0; r < 4; r++)
            #pragma unroll
            for (int k4 = 0; k4 < 2; k4++)
                xv[r][k4] = xw[(size_t)(q * 4 + r) * 64 + lane + 32 * k4];

        ull a[4][8];
        #pragma unroll
        for (int r = 0; r < 4; r++)
            #pragma unroll
            for (int n8 = 0; n8 < 8; n8++) a[r][n8] = 0ull;

        #pragma unroll
        for (int k4 = 0; k4 < 2; k4++) {
            const int d4 = lane + 32 * k4;
            #pragma unroll
            for (int n8 = 0; n8 < 8; n8++) {
                const ulonglong2 bv = bdu[(nh * 8 + n8) * 64 + d4];
                #pragma unroll
                for (int r = 0; r < 4; r++) {
                    fma2(a[r][n8], xv[r][k4].x, bv.x);
                    fma2(a[r][n8], xv[r][k4].y, bv.y);
                }
            }
        }

        float fa[32];
        #pragma unroll
        for (int r = 0; r < 4; r++)
            #pragma unroll
            for (int n8 = 0; n8 < 8; n8++) fa[r * 8 + n8] = fold2(a[r][n8]);

        const float res = mv_reduce32(fa, lane);
        Wbuf[(rg * 32 + q * 4 + (lane >> 3)) * 16 + nh * 8 + (lane & 7)] = res;
    }
    __syncthreads();

    float Ad = 0.f;
    if (lane < 16) {
        Ad = expf(-DTF * fabsf(A[lane]));
        float p = 0.f;
        #pragma unroll
        for (int r = 0; r < 16; r++) {
            const int j = warp * 16 + r;
            p = fmaf(p, Ad, Wbuf[j * 16 + lane]);
            Wbuf[j * 16 + lane] = p;
        }
        sub[warp * 16 + lane] = p;
    }
    __syncthreads();

    if (warp == 0 && lane < 16) {
        float AL16 = Ad;
        #pragma unroll
        for (int t = 0; t < 4; t++) AL16 *= AL16;
        float run = 0.f;
        #pragma unroll
        for (int w = 0; w < 8; w++) {
            pre[w * 16 + lane] = run;
            run = fmaf(run, AL16, sub[w * 16 + lane]);
        }
        g_carry[(b * NC + c) * N + lane] = run;
    }
    __syncthreads();

    if (lane < 16 && warp > 0) {
        const float pref = pre[warp * 16 + lane];
        float f = Ad;
        #pragma unroll
        for (int r = 0; r < 16; r++) {
            const int j = warp * 16 + r;
            Wbuf[j * 16 + lane] = fmaf(f, pref, Wbuf[j * 16 + lane]);
            f *= Ad;
        }
    }
    __syncthreads();

    float4* pg = reinterpret_cast<float4*>(g_p + (size_t)(b * S + c * L) * N);
    const float4* wb = reinterpret_cast<const float4*>(Wbuf);
    for (int idx = tid; idx < L * N / 4; idx += 256) pg[idx] = wb[idx];
}

// ---------------------------------------------------------------------------
// Kernel C v4: R=8 row tiling (each Cm LDS.128 feeds 8 rows) — targets the
// L1tex wavefront bound. h precomputed for all 16 rows, read via uniform LDS.
// ---------------------------------------------------------------------------
__global__ void __launch_bounds__(256, 2) kC(const float* __restrict__ x,
                                             const float* __restrict__ A,
                                             const float* __restrict__ Cm,
                                             const float* __restrict__ Dv,
                                             const float* __restrict__ gamma,
                                             const float* __restrict__ beta,
                                             float* __restrict__ out) {
    __shared__ ulonglong2 cm4s[64 * 17];           // packed Cm^T (pad 17)
    __shared__ ull hsp[L * N];                     // splatted h states (16 KB)
    __shared__ ulonglong2 dvs4[64], gs4[64], bs4[64];
    __shared__ float part[31 * N];
    __shared__ float hin_s[N];

    const int c = blockIdx.x, b = blockIdx.y;
    const int tid = threadIdx.x, lane = tid & 31, warp = tid >> 5;

    {
        float* cmf = reinterpret_cast<float*>(cm4s);
        for (int idx = tid; idx < N * D; idx += 256) {
            const int d = idx >> 4, n = idx & 15;      // Cm is [D][N] row-major
            cmf[((d >> 2) * 17 + n) * 4 + (d & 3)] = Cm[idx];
        }
        float* dvf = reinterpret_cast<float*>(dvs4);
        float* gf  = reinterpret_cast<float*>(gs4);
        float* bf  = reinterpret_cast<float*>(bs4);
        if (tid < D) { dvf[tid] = Dv[tid]; gf[tid] = gamma[tid]; bf[tid] = beta[tid]; }
    }

    // ---- Inter-chunk carry ----
    if (c > 0) {
        const int n = tid & 15, cc0 = tid >> 4;
        const float Adn = expf(-DTF * fabsf(A[n]));
        float AL = Adn;
        #pragma unroll
        for (int t = 0; t < 7; t++) AL *= AL;          // Ad^128
        #pragma unroll
        for (int rep = 0; rep < 2; rep++) {
            const int cc = cc0 + rep * 16;
            if (cc < c) {
                int e = c - 1 - cc;
                float wgt = 1.f, base = AL;
                while (e) { if (e & 1) wgt *= base; base *= base; e >>= 1; }
                part[cc * 16 + n] = wgt * g_carry[(b * NC + cc) * N + n];
            }
        }
    }
    __syncthreads();
    if (warp == 0 && lane < 16) {
        float h = 0.f;
        for (int cc = 0; cc < c; cc++) h += part[cc * 16 + lane];
        hin_s[lane] = h;
    }
    __syncthreads();

    const float hin = hin_s[lane & 15];
    const float Ad  = expf(-DTF * fabsf(A[lane & 15]));
    float Ad16 = Ad * Ad; Ad16 *= Ad16; Ad16 *= Ad16; Ad16 *= Ad16;   // Ad^16
    float f = Ad;
    for (int w = 0; w < warp; w++) f *= Ad16;          // Ad^(warp*16+1)

    const size_t rowBase = (size_t)(b * S) + c * L + warp * 16;
    const ulonglong2* xw = reinterpret_cast<const ulonglong2*>(x + rowBase * D);
    const float* pw = g_p + rowBase * N;
    ull* hw = hsp + (size_t)warp * 16 * N;             // this warp's 16 rows

    // ---- Precompute h for all 16 rows, splatted into smem ----
    {
        float pv[16];
        #pragma unroll
        for (int r = 0; r < 16; r++) pv[r] = pw[r * 16 + (lane & 15)];
        if (lane < 16) {
            float fr = f;
            #pragma unroll
            for (int r = 0; r < 16; r++) {
                hw[r * 16 + lane] = splat2(clip10(fmaf(fr, hin, pv[r])));
                fr *= Ad;
            }
        }
    }
    __syncwarp();

    const ulonglong2* hrow2 = reinterpret_cast<const ulonglong2*>(hw);

    #pragma unroll 1
    for (int pass = 0; pass < 2; pass++) {
        const int row0 = pass * 8;

        // ---- y init: u * Dv, staged in 2-row batches ----
        ull y[8][4];
        {
            const ulonglong2 dv0 = dvs4[lane];
            const ulonglong2 dv1 = dvs4[32 + lane];
            #pragma unroll
            for (int rb = 0; rb < 4; rb++) {
                ulonglong2 xa[2], xb[2];
                const size_t base = (size_t)(row0 + rb * 2) * 64;
                xa[0] = xw[base + lane];        xa[1] = xw[base + 32 + lane];
                xb[0] = xw[base + 64 + lane];   xb[1] = xw[base + 96 + lane];
                y[rb * 2][0]     = mul2(xa[0].x, dv0.x);
                y[rb * 2][1]     = mul2(xa[0].y, dv0.y);
                y[rb * 2][2]     = mul2(xa[1].x, dv1.x);
                y[rb * 2][3]     = mul2(xa[1].y, dv1.y);
                y[rb * 2 + 1][0] = mul2(xb[0].x, dv0.x);
                y[rb * 2 + 1][1] = mul2(xb[0].y, dv0.y);
                y[rb * 2 + 1][2] = mul2(xb[1].x, dv1.x);
                y[rb * 2 + 1][3] = mul2(xb[1].y, dv1.y);
            }
        }

        // ---- GEMM: n-pairs; each cv LDS.128 feeds 8 rows ----
        #pragma unroll
        for (int np = 0; np < 8; np++) {
            const ulonglong2 cv0a = cm4s[lane * 17 + 2 * np];
            const ulonglong2 cv0b = cm4s[lane * 17 + 2 * np + 1];
            const ulonglong2 cv1a = cm4s[(32 + lane) * 17 + 2 * np];
            const ulonglong2 cv1b = cm4s[(32 + lane) * 17 + 2 * np + 1];
            #pragma unroll
            for (int r = 0; r < 8; r++) {
                const ulonglong2 hp = hrow2[(row0 + r) * 8 + np];  // uniform
                fma2(y[r][0], hp.x, cv0a.x);
                fma2(y[r][1], hp.x, cv0a.y);
                fma2(y[r][2], hp.x, cv1a.x);
                fma2(y[r][3], hp.x, cv1a.y);
                fma2(y[r][0], hp.y, cv0b.x);
                fma2(y[r][1], hp.y, cv0b.y);
                fma2(y[r][2], hp.y, cv1b.x);
                fma2(y[r][3], hp.y, cv1b.y);
            }
        }

        // ---- LayerNorm stats ----
        float s[8], ss[8];
        #pragma unroll
        for (int r = 0; r < 8; r++) {
            s[r] = fold2(add2(add2(y[r][0], y[r][1]), add2(y[r][2], y[r][3])));
            ull qacc = 0ull;
            #pragma unroll
            for (int k = 0; k < 4; k++) fma2(qacc, y[r][k], y[r][k]);
            ss[r] = fold2(qacc);
        }
        #pragma unroll
        for (int off = 16; off >= 1; off >>= 1) {
            #pragma unroll
            for (int r = 0; r < 8; r++) {
                s[r]  += __shfl_xor_sync(0xffffffffu, s[r], off);
                ss[r] += __shfl_xor_sync(0xffffffffu, ss[r], off);
            }
        }

        // ---- Normalize + store ----
        #pragma unroll
        for (int r = 0; r < 8; r++) {
            const float mu = s[r] * (1.0f / 256.0f);
            const float rv = rsqrtf(fmaf(ss[r], 1.0f / 256.0f, -mu * mu) + LN_EPS);
            const ull rp = splat2(rv), mp = splat2(-mu * rv);

            ulonglong2* o = reinterpret_cast<ulonglong2*>(out + (rowBase + row0 + r) * D);
            ulonglong2 w0, w1;
            {
                const ulonglong2 g0 = gs4[lane], b0 = bs4[lane];
                w0.x = fma2g(fma2g(y[r][0], rp, mp), g0.x, b0.x);
                w0.y = fma2g(fma2g(y[r][1], rp, mp), g0.y, b0.y);
            }
            {
                const ulonglong2 g1 = gs4[32 + lane], b1 = bs4[32 + lane];
                w1.x = fma2g(fma2g(y[r][2], rp, mp), g1.x, b1.x);
                w1.y = fma2g(fma2g(y[r][3], rp, mp), g1.y, b1.y);
            }
            o[lane]      = w0;
            o[32 + lane] = w1;
        }
    }
}

extern "C" void kernel_launch(void* const* d_in, const int* in_sizes, int n_in,
                              void* d_out, int out_size) {
    const float* x     = (const float*)d_in[0];
    const float* A     = (const float*)d_in[1];
    const float* Bm    = (const float*)d_in[2];
    const float* Cm    = (const float*)d_in[3];
    const float* Dv    = (const float*)d_in[4];
    const float* gamma = (const float*)d_in[5];
    const float* beta  = (const float*)d_in[6];
    float* out = (float*)d_out;

    kA<<<dim3(NC, Bb), 256>>>(x, A, Bm);
    kC<<<dim3(NC, Bb), 256>>>(x, A, Cm, Dv, gamma, beta, out);
}

// round 10
// speedup vs baseline: 1.6976x; 1.6976x over previous
#include <cuda_runtime.h>
#include <math.h>

#define DTF 1e-4f
#define LN_EPS 1e-5f

constexpr int Bb = 16;    // batch
constexpr int S  = 4096;  // sequence
constexpr int D  = 256;   // model dim
constexpr int N  = 16;    // state dim
constexpr int L  = 128;   // chunk length
constexpr int NC = S / L; // 32 chunks per batch

__device__ float g_p[Bb * S * N];        // local prefix states (4 MB)
__device__ float g_carry[Bb * NC * N];   // per-chunk carries

typedef unsigned long long ull;

__device__ __forceinline__ void fma2(ull& d, ull a, ull b) {
    asm("fma.rn.f32x2 %0, %1, %2, %0;" : "+l"(d) : "l"(a), "l"(b));
}
__device__ __forceinline__ ull fma2g(ull a, ull b, ull c) {
    ull d; asm("fma.rn.f32x2 %0, %1, %2, %3;" : "=l"(d) : "l"(a), "l"(b), "l"(c)); return d;
}
__device__ __forceinline__ ull mul2(ull a, ull b) {
    ull d; asm("mul.rn.f32x2 %0, %1, %2;" : "=l"(d) : "l"(a), "l"(b)); return d;
}
__device__ __forceinline__ ull add2(ull a, ull b) {
    ull d; asm("add.rn.f32x2 %0, %1, %2;" : "=l"(d) : "l"(a), "l"(b)); return d;
}
__device__ __forceinline__ ull splat2(float v) {
    ull r; asm("mov.b64 %0, {%1, %1};" : "=l"(r) : "f"(v)); return r;
}
__device__ __forceinline__ float fold2(ull v) {
    float lo, hi; asm("mov.b64 {%0, %1}, %2;" : "=f"(lo), "=f"(hi) : "l"(v));
    return lo + hi;
}

__device__ __forceinline__ float clip10(float v) {
    return fminf(fmaxf(v, -10.0f), 10.0f);
}

// 32-value butterfly reduction: lane l ends with the full 32-lane sum of v[l].
__device__ __forceinline__ float mv_reduce32(float v[32], int lane) {
    {
        const bool hb = (lane & 16) != 0;
        #pragma unroll
        for (int t = 0; t < 16; t++) {
            float keep = hb ? v[t + 16] : v[t];
            float send = hb ? v[t] : v[t + 16];
            v[t] = keep + __shfl_xor_sync(0xffffffffu, send, 16);
        }
    }
    {
        const bool hb = (lane & 8) != 0;
        #pragma unroll
        for (int t = 0; t < 8; t++) {
            float keep = hb ? v[t + 8] : v[t];
            float send = hb ? v[t] : v[t + 8];
            v[t] = keep + __shfl_xor_sync(0xffffffffu, send, 8);
        }
    }
    {
        const bool hb = (lane & 4) != 0;
        #pragma unroll
        for (int t = 0; t < 4; t++) {
            float keep = hb ? v[t + 4] : v[t];
            float send = hb ? v[t] : v[t + 4];
            v[t] = keep + __shfl_xor_sync(0xffffffffu, send, 4);
        }
    }
    {
        const bool hb = (lane & 2) != 0;
        #pragma unroll
        for (int t = 0; t < 2; t++) {
            float keep = hb ? v[t + 2] : v[t];
            float send = hb ? v[t] : v[t + 2];
            v[t] = keep + __shfl_xor_sync(0xffffffffu, send, 2);
        }
    }
    {
        const bool hb = (lane & 1) != 0;
        float keep = hb ? v[1] : v[0];
        float send = hb ? v[0] : v[1];
        v[0] = keep + __shfl_xor_sync(0xffffffffu, send, 1);
    }
    return v[0];
}

// ---------------------------------------------------------------------------
// Kernel A (unchanged): warp-split GEMM + 2-level local scan.
// ---------------------------------------------------------------------------
__global__ void __launch_bounds__(256, 2) kA(const float* __restrict__ x,
                                             const float* __restrict__ A,
                                             const float* __restrict__ Bm) {
    __shared__ float bd[N * D];        // bd[n*256+d] = DT*Bm[n][d]
    __shared__ float Wbuf[L * N];
    __shared__ float sub[8 * N], pre[8 * N];

    const int c = blockIdx.x, b = blockIdx.y;
    const int tid = threadIdx.x, lane = tid & 31, warp = tid >> 5;
    const int rg = warp >> 1, nh = warp & 1;

    {
        const float4* Bm4 = reinterpret_cast<const float4*>(Bm);
        float4* bd4 = reinterpret_cast<float4*>(bd);
        for (int idx = tid; idx < N * D / 4; idx += 256) {
            float4 v = Bm4[idx];
            v.x *= DTF; v.y *= DTF; v.z *= DTF; v.w *= DTF;
            bd4[idx] = v;
        }
    }
    __syncthreads();

    const ulonglong2* xw = reinterpret_cast<const ulonglong2*>(
        x + (size_t)(b * S + c * L + rg * 32) * D);
    const ulonglong2* bdu = reinterpret_cast<const ulonglong2*>(bd);

    #pragma unroll 1
    for (int q = 0; q < 8; q++) {
        ulonglong2 xv[4][2];
        #pragma unroll
        for (int r = 0; r < 4; r++)
            #pragma unroll
            for (int k4 = 0; k4 < 2; k4++)
                xv[r][k4] = xw[(size_t)(q * 4 + r) * 64 + lane + 32 * k4];

        ull a[4][8];
        #pragma unroll
        for (int r = 0; r < 4; r++)
            #pragma unroll
            for (int n8 = 0; n8 < 8; n8++) a[r][n8] = 0ull;

        #pragma unroll
        for (int k4 = 0; k4 < 2; k4++) {
            const int d4 = lane + 32 * k4;
            #pragma unroll
            for (int n8 = 0; n8 < 8; n8++) {
                const ulonglong2 bv = bdu[(nh * 8 + n8) * 64 + d4];
                #pragma unroll
                for (int r = 0; r < 4; r++) {
                    fma2(a[r][n8], xv[r][k4].x, bv.x);
                    fma2(a[r][n8], xv[r][k4].y, bv.y);
                }
            }
        }

        float fa[32];
        #pragma unroll
        for (int r = 0; r < 4; r++)
            #pragma unroll
            for (int n8 = 0; n8 < 8; n8++) fa[r * 8 + n8] = fold2(a[r][n8]);

        const float res = mv_reduce32(fa, lane);
        Wbuf[(rg * 32 + q * 4 + (lane >> 3)) * 16 + nh * 8 + (lane & 7)] = res;
    }
    __syncthreads();

    float Ad = 0.f;
    if (lane < 16) {
        Ad = expf(-DTF * fabsf(A[lane]));
        float p = 0.f;
        #pragma unroll
        for (int r = 0; r < 16; r++) {
            const int j = warp * 16 + r;
            p = fmaf(p, Ad, Wbuf[j * 16 + lane]);
            Wbuf[j * 16 + lane] = p;
        }
        sub[warp * 16 + lane] = p;
    }
    __syncthreads();

    if (warp == 0 && lane < 16) {
        float AL16 = Ad;
        #pragma unroll
        for (int t = 0; t < 4; t++) AL16 *= AL16;
        float run = 0.f;
        #pragma unroll
        for (int w = 0; w < 8; w++) {
            pre[w * 16 + lane] = run;
            run = fmaf(run, AL16, sub[w * 16 + lane]);
        }
        g_carry[(b * NC + c) * N + lane] = run;
    }
    __syncthreads();

    if (lane < 16 && warp > 0) {
        const float pref = pre[warp * 16 + lane];
        float f = Ad;
        #pragma unroll
        for (int r = 0; r < 16; r++) {
            const int j = warp * 16 + r;
            Wbuf[j * 16 + lane] = fmaf(f, pref, Wbuf[j * 16 + lane]);
            f *= Ad;
        }
    }
    __syncthreads();

    float4* pg = reinterpret_cast<float4*>(g_p + (size_t)(b * S + c * L) * N);
    const float4* wb = reinterpret_cast<const float4*>(Wbuf);
    for (int idx = tid; idx < L * N / 4; idx += 256) pg[idx] = wb[idx];
}

// ---------------------------------------------------------------------------
// Kernel C v5: R=8 row tiling at __launch_bounds__(256,1) — full register
// budget (no spills). Each Cm LDS.128 feeds 8 rows; h via uniform LDS.
// ---------------------------------------------------------------------------
__global__ void __launch_bounds__(256, 1) kC(const float* __restrict__ x,
                                             const float* __restrict__ A,
                                             const float* __restrict__ Cm,
                                             const float* __restrict__ Dv,
                                             const float* __restrict__ gamma,
                                             const float* __restrict__ beta,
                                             float* __restrict__ out) {
    __shared__ ulonglong2 cm4s[64 * 17];           // packed Cm^T (pad 17)
    __shared__ ull hsp[L * N];                     // splatted h states (16 KB)
    __shared__ ulonglong2 dvs4[64], gs4[64], bs4[64];
    __shared__ float part[31 * N];
    __shared__ float hin_s[N];

    const int c = blockIdx.x, b = blockIdx.y;
    const int tid = threadIdx.x, lane = tid & 31, warp = tid >> 5;

    {
        float* cmf = reinterpret_cast<float*>(cm4s);
        for (int idx = tid; idx < N * D; idx += 256) {
            const int d = idx >> 4, n = idx & 15;      // Cm is [D][N] row-major
            cmf[((d >> 2) * 17 + n) * 4 + (d & 3)] = Cm[idx];
        }
        float* dvf = reinterpret_cast<float*>(dvs4);
        float* gf  = reinterpret_cast<float*>(gs4);
        float* bf  = reinterpret_cast<float*>(bs4);
        if (tid < D) { dvf[tid] = Dv[tid]; gf[tid] = gamma[tid]; bf[tid] = beta[tid]; }
    }

    // ---- Inter-chunk carry ----
    if (c > 0) {
        const int n = tid & 15, cc0 = tid >> 4;
        const float Adn = expf(-DTF * fabsf(A[n]));
        float AL = Adn;
        #pragma unroll
        for (int t = 0; t < 7; t++) AL *= AL;          // Ad^128
        #pragma unroll
        for (int rep = 0; rep < 2; rep++) {
            const int cc = cc0 + rep * 16;
            if (cc < c) {
                int e = c - 1 - cc;
                float wgt = 1.f, base = AL;
                while (e) { if (e & 1) wgt *= base; base *= base; e >>= 1; }
                part[cc * 16 + n] = wgt * g_carry[(b * NC + cc) * N + n];
            }
        }
    }
    __syncthreads();
    if (warp == 0 && lane < 16) {
        float h = 0.f;
        for (int cc = 0; cc < c; cc++) h += part[cc * 16 + lane];
        hin_s[lane] = h;
    }
    __syncthreads();

    const float hin = hin_s[lane & 15];
    const float Ad  = expf(-DTF * fabsf(A[lane & 15]));
    float Ad16 = Ad * Ad; Ad16 *= Ad16; Ad16 *= Ad16; Ad16 *= Ad16;   // Ad^16
    float f = Ad;
    for (int w = 0; w < warp; w++) f *= Ad16;          // Ad^(warp*16+1)

    const size_t rowBase = (size_t)(b * S) + c * L + warp * 16;
    const ulonglong2* xw = reinterpret_cast<const ulonglong2*>(x + rowBase * D);
    const float* pw = g_p + rowBase * N;
    ull* hw = hsp + (size_t)warp * 16 * N;             // this warp's 16 rows

    // ---- Precompute h for all 16 rows, splatted into smem ----
    {
        float pv[16];
        #pragma unroll
        for (int r = 0; r < 16; r++) pv[r] = pw[r * 16 + (lane & 15)];
        if (lane < 16) {
            float fr = f;
            #pragma unroll
            for (int r = 0; r < 16; r++) {
                hw[r * 16 + lane] = splat2(clip10(fmaf(fr, hin, pv[r])));
                fr *= Ad;
            }
        }
    }
    __syncwarp();

    const ulonglong2* hrow2 = reinterpret_cast<const ulonglong2*>(hw);

    #pragma unroll 1
    for (int pass = 0; pass < 2; pass++) {
        const int row0 = pass * 8;

        // ---- y init: u * Dv, staged in 2-row batches ----
        ull y[8][4];
        {
            const ulonglong2 dv0 = dvs4[lane];
            const ulonglong2 dv1 = dvs4[32 + lane];
            #pragma unroll
            for (int rb = 0; rb < 4; rb++) {
                ulonglong2 xa[2], xb[2];
                const size_t base = (size_t)(row0 + rb * 2) * 64;
                xa[0] = xw[base + lane];        xa[1] = xw[base + 32 + lane];
                xb[0] = xw[base + 64 + lane];   xb[1] = xw[base + 96 + lane];
                y[rb * 2][0]     = mul2(xa[0].x, dv0.x);
                y[rb * 2][1]     = mul2(xa[0].y, dv0.y);
                y[rb * 2][2]     = mul2(xa[1].x, dv1.x);
                y[rb * 2][3]     = mul2(xa[1].y, dv1.y);
                y[rb * 2 + 1][0] = mul2(xb[0].x, dv0.x);
                y[rb * 2 + 1][1] = mul2(xb[0].y, dv0.y);
                y[rb * 2 + 1][2] = mul2(xb[1].x, dv1.x);
                y[rb * 2 + 1][3] = mul2(xb[1].y, dv1.y);
            }
        }

        // ---- GEMM: n-pairs; each cv LDS.128 feeds 8 rows ----
        #pragma unroll
        for (int np = 0; np < 8; np++) {
            const ulonglong2 cv0a = cm4s[lane * 17 + 2 * np];
            const ulonglong2 cv0b = cm4s[lane * 17 + 2 * np + 1];
            const ulonglong2 cv1a = cm4s[(32 + lane) * 17 + 2 * np];
            const ulonglong2 cv1b = cm4s[(32 + lane) * 17 + 2 * np + 1];
            #pragma unroll
            for (int r = 0; r < 8; r++) {
                const ulonglong2 hp = hrow2[(row0 + r) * 8 + np];  // uniform
                fma2(y[r][0], hp.x, cv0a.x);
                fma2(y[r][1], hp.x, cv0a.y);
                fma2(y[r][2], hp.x, cv1a.x);
                fma2(y[r][3], hp.x, cv1a.y);
                fma2(y[r][0], hp.y, cv0b.x);
                fma2(y[r][1], hp.y, cv0b.y);
                fma2(y[r][2], hp.y, cv1b.x);
                fma2(y[r][3], hp.y, cv1b.y);
            }
        }

        // ---- LayerNorm stats ----
        float s[8], ss[8];
        #pragma unroll
        for (int r = 0; r < 8; r++) {
            s[r] = fold2(add2(add2(y[r][0], y[r][1]), add2(y[r][2], y[r][3])));
            ull qacc = 0ull;
            #pragma unroll
            for (int k = 0; k < 4; k++) fma2(qacc, y[r][k], y[r][k]);
            ss[r] = fold2(qacc);
        }
        #pragma unroll
        for (int off = 16; off >= 1; off >>= 1) {
            #pragma unroll
            for (int r = 0; r < 8; r++) {
                s[r]  += __shfl_xor_sync(0xffffffffu, s[r], off);
                ss[r] += __shfl_xor_sync(0xffffffffu, ss[r], off);
            }
        }

        // ---- Normalize + store ----
        #pragma unroll
        for (int r = 0; r < 8; r++) {
            const float mu = s[r] * (1.0f / 256.0f);
            const float rv = rsqrtf(fmaf(ss[r], 1.0f / 256.0f, -mu * mu) + LN_EPS);
            const ull rp = splat2(rv), mp = splat2(-mu * rv);

            ulonglong2* o = reinterpret_cast<ulonglong2*>(out + (rowBase + row0 + r) * D);
            ulonglong2 w0, w1;
            {
                const ulonglong2 g0 = gs4[lane], b0 = bs4[lane];
                w0.x = fma2g(fma2g(y[r][0], rp, mp), g0.x, b0.x);
                w0.y = fma2g(fma2g(y[r][1], rp, mp), g0.y, b0.y);
            }
            {
                const ulonglong2 g1 = gs4[32 + lane], b1 = bs4[32 + lane];
                w1.x = fma2g(fma2g(y[r][2], rp, mp), g1.x, b1.x);
                w1.y = fma2g(fma2g(y[r][3], rp, mp), g1.y, b1.y);
            }
            o[lane]      = w0;
            o[32 + lane] = w1;
        }
    }
}

extern "C" void kernel_launch(void* const* d_in, const int* in_sizes, int n_in,
                              void* d_out, int out_size) {
    const float* x     = (const float*)d_in[0];
    const float* A     = (const float*)d_in[1];
    const float* Bm    = (const float*)d_in[2];
    const float* Cm    = (const float*)d_in[3];
    const float* Dv    = (const float*)d_in[4];
    const float* gamma = (const float*)d_in[5];
    const float* beta  = (const float*)d_in[6];
    float* out = (float*)d_out;

    kA<<<dim3(NC, Bb), 256>>>(x, A, Bm);
    kC<<<dim3(NC, Bb), 256>>>(x, A, Cm, Dv, gamma, beta, out);
}

// round 11
// speedup vs baseline: 1.9546x; 1.1514x over previous
#include <cuda_runtime.h>
#include <math.h>

#define DTF 1e-4f
#define LN_EPS 1e-5f

constexpr int Bb = 16;    // batch
constexpr int S  = 4096;  // sequence
constexpr int D  = 256;   // model dim
constexpr int N  = 16;    // state dim
constexpr int L  = 128;   // chunk length
constexpr int NC = S / L; // 32 chunks per batch
constexpr int WST = 20;   // Wbuf row stride (conflict-free scatter)

__device__ float g_p[Bb * S * N];        // local prefix states (4 MB)
__device__ float g_carry[Bb * NC * N];   // per-chunk carries

typedef unsigned long long ull;

__device__ __forceinline__ void fma2(ull& d, ull a, ull b) {
    asm("fma.rn.f32x2 %0, %1, %2, %0;" : "+l"(d) : "l"(a), "l"(b));
}
__device__ __forceinline__ ull fma2g(ull a, ull b, ull c) {
    ull d; asm("fma.rn.f32x2 %0, %1, %2, %3;" : "=l"(d) : "l"(a), "l"(b), "l"(c)); return d;
}
__device__ __forceinline__ ull mul2(ull a, ull b) {
    ull d; asm("mul.rn.f32x2 %0, %1, %2;" : "=l"(d) : "l"(a), "l"(b)); return d;
}
__device__ __forceinline__ ull add2(ull a, ull b) {
    ull d; asm("add.rn.f32x2 %0, %1, %2;" : "=l"(d) : "l"(a), "l"(b)); return d;
}
__device__ __forceinline__ ull splat2(float v) {
    ull r; asm("mov.b64 %0, {%1, %1};" : "=l"(r) : "f"(v)); return r;
}
__device__ __forceinline__ float fold2(ull v) {
    float lo, hi; asm("mov.b64 {%0, %1}, %2;" : "=f"(lo), "=f"(hi) : "l"(v));
    return lo + hi;
}

__device__ __forceinline__ float clip10(float v) {
    return fminf(fmaxf(v, -10.0f), 10.0f);
}

// 32-value butterfly reduction: lane l ends with the full 32-lane sum of v[l].
__device__ __forceinline__ float mv_reduce32(float v[32], int lane) {
    {
        const bool hb = (lane & 16) != 0;
        #pragma unroll
        for (int t = 0; t < 16; t++) {
            float keep = hb ? v[t + 16] : v[t];
            float send = hb ? v[t] : v[t + 16];
            v[t] = keep + __shfl_xor_sync(0xffffffffu, send, 16);
        }
    }
    {
        const bool hb = (lane & 8) != 0;
        #pragma unroll
        for (int t = 0; t < 8; t++) {
            float keep = hb ? v[t + 8] : v[t];
            float send = hb ? v[t] : v[t + 8];
            v[t] = keep + __shfl_xor_sync(0xffffffffu, send, 8);
        }
    }
    {
        const bool hb = (lane & 4) != 0;
        #pragma unroll
        for (int t = 0; t < 4; t++) {
            float keep = hb ? v[t + 4] : v[t];
            float send = hb ? v[t] : v[t + 4];
            v[t] = keep + __shfl_xor_sync(0xffffffffu, send, 4);
        }
    }
    {
        const bool hb = (lane & 2) != 0;
        #pragma unroll
        for (int t = 0; t < 2; t++) {
            float keep = hb ? v[t + 2] : v[t];
            float send = hb ? v[t] : v[t + 2];
            v[t] = keep + __shfl_xor_sync(0xffffffffu, send, 2);
        }
    }
    {
        const bool hb = (lane & 1) != 0;
        float keep = hb ? v[1] : v[0];
        float send = hb ? v[0] : v[1];
        v[0] = keep + __shfl_xor_sync(0xffffffffu, send, 1);
    }
    return v[0];
}

// ---------------------------------------------------------------------------
// Kernel A v3: warp = (n-quarter, row-half). 8-row tiles: each bd LDS.128
// feeds 8 rows (bd wavefronts halved). x staged per k4-phase (regs ~110).
// ---------------------------------------------------------------------------
__global__ void __launch_bounds__(256, 2) kA(const float* __restrict__ x,
                                             const float* __restrict__ A,
                                             const float* __restrict__ Bm) {
    __shared__ float bd[N * D];        // bd[n*256+d] = DT*Bm[n][d]
    __shared__ float Wbuf[L * WST];    // stride-20 rows (conflict-free)
    __shared__ float sub[8 * N], pre[8 * N];

    const int c = blockIdx.x, b = blockIdx.y;
    const int tid = threadIdx.x, lane = tid & 31, warp = tid >> 5;
    const int nq = warp & 3, rh = warp >> 2;

    {
        const float4* Bm4 = reinterpret_cast<const float4*>(Bm);
        float4* bd4 = reinterpret_cast<float4*>(bd);
        for (int idx = tid; idx < N * D / 4; idx += 256) {
            float4 v = Bm4[idx];
            v.x *= DTF; v.y *= DTF; v.z *= DTF; v.w *= DTF;
            bd4[idx] = v;
        }
    }
    __syncthreads();

    const ulonglong2* xw = reinterpret_cast<const ulonglong2*>(
        x + (size_t)(b * S + c * L + rh * 64) * D);      // 64 rows; 64 u2/row
    const ulonglong2* bdu = reinterpret_cast<const ulonglong2*>(bd);

    #pragma unroll 1
    for (int q = 0; q < 8; q++) {
        ull a[8][4];
        #pragma unroll
        for (int r = 0; r < 8; r++)
            #pragma unroll
            for (int n4 = 0; n4 < 4; n4++) a[r][n4] = 0ull;

        #pragma unroll
        for (int k4 = 0; k4 < 2; k4++) {
            // Stage this k4-phase's x for all 8 rows (8 LDG.128, MLP=8)
            ulonglong2 xv[8];
            #pragma unroll
            for (int r = 0; r < 8; r++)
                xv[r] = xw[(size_t)(q * 8 + r) * 64 + k4 * 32 + lane];

            const int d4 = lane + 32 * k4;
            #pragma unroll
            for (int n4 = 0; n4 < 4; n4++) {
                const ulonglong2 bv = bdu[(nq * 4 + n4) * 64 + d4];
                #pragma unroll
                for (int r = 0; r < 8; r++) {
                    fma2(a[r][n4], xv[r].x, bv.x);
                    fma2(a[r][n4], xv[r].y, bv.y);
                }
            }
        }

        float fa[32];
        #pragma unroll
        for (int r = 0; r < 8; r++)
            #pragma unroll
            for (int n4 = 0; n4 < 4; n4++) fa[r * 4 + n4] = fold2(a[r][n4]);

        const float res = mv_reduce32(fa, lane);
        // lane l -> row offset r = l>>2, n-sub = l&3
        Wbuf[(rh * 64 + q * 8 + (lane >> 2)) * WST + nq * 4 + (lane & 3)] = res;
    }
    __syncthreads();

    // ---- Level-1 scan: each warp scans its own 16 rows ----
    float Ad = 0.f;
    if (lane < 16) {
        Ad = expf(-DTF * fabsf(A[lane]));
        float p = 0.f;
        #pragma unroll
        for (int r = 0; r < 16; r++) {
            const int j = warp * 16 + r;
            p = fmaf(p, Ad, Wbuf[j * WST + lane]);
            Wbuf[j * WST + lane] = p;
        }
        sub[warp * 16 + lane] = p;
    }
    __syncthreads();

    if (warp == 0 && lane < 16) {
        float AL16 = Ad;
        #pragma unroll
        for (int t = 0; t < 4; t++) AL16 *= AL16;   // Ad^16
        float run = 0.f;
        #pragma unroll
        for (int w = 0; w < 8; w++) {
            pre[w * 16 + lane] = run;
            run = fmaf(run, AL16, sub[w * 16 + lane]);
        }
        g_carry[(b * NC + c) * N + lane] = run;
    }
    __syncthreads();

    if (lane < 16 && warp > 0) {
        const float pref = pre[warp * 16 + lane];
        float f = Ad;
        #pragma unroll
        for (int r = 0; r < 16; r++) {
            const int j = warp * 16 + r;
            Wbuf[j * WST + lane] = fmaf(f, pref, Wbuf[j * WST + lane]);
            f *= Ad;
        }
    }
    __syncthreads();

    // Copy to g_p (vector stores; strided smem reads)
    float4* pg4 = reinterpret_cast<float4*>(g_p + (size_t)(b * S + c * L) * N);
    for (int idx = tid; idx < L * 4; idx += 256) {
        const int j = idx >> 2, n4 = idx & 3;
        float4 v;
        v.x = Wbuf[j * WST + n4 * 4 + 0];
        v.y = Wbuf[j * WST + n4 * 4 + 1];
        v.z = Wbuf[j * WST + n4 * 4 + 2];
        v.w = Wbuf[j * WST + n4 * 4 + 3];
        pg4[j * 4 + n4] = v;
    }
}

// ---------------------------------------------------------------------------
// Kernel C (round-8 proven version): R=4 quads, smem-splatted h, occ 3.
// ---------------------------------------------------------------------------
__global__ void __launch_bounds__(256, 3) kC(const float* __restrict__ x,
                                             const float* __restrict__ A,
                                             const float* __restrict__ Cm,
                                             const float* __restrict__ Dv,
                                             const float* __restrict__ gamma,
                                             const float* __restrict__ beta,
                                             float* __restrict__ out) {
    __shared__ ulonglong2 cm4s[64 * 17];           // packed Cm^T (pad 17)
    __shared__ ull hsp[L * N];                     // splatted h states (16 KB)
    __shared__ ulonglong2 dvs4[64], gs4[64], bs4[64];
    __shared__ float part[31 * N];
    __shared__ float hin_s[N];

    const int c = blockIdx.x, b = blockIdx.y;
    const int tid = threadIdx.x, lane = tid & 31, warp = tid >> 5;

    {
        float* cmf = reinterpret_cast<float*>(cm4s);
        for (int idx = tid; idx < N * D; idx += 256) {
            const int d = idx >> 4, n = idx & 15;      // Cm is [D][N] row-major
            cmf[((d >> 2) * 17 + n) * 4 + (d & 3)] = Cm[idx];
        }
        float* dvf = reinterpret_cast<float*>(dvs4);
        float* gf  = reinterpret_cast<float*>(gs4);
        float* bf  = reinterpret_cast<float*>(bs4);
        if (tid < D) { dvf[tid] = Dv[tid]; gf[tid] = gamma[tid]; bf[tid] = beta[tid]; }
    }

    // ---- Inter-chunk carry ----
    if (c > 0) {
        const int n = tid & 15, cc0 = tid >> 4;
        const float Adn = expf(-DTF * fabsf(A[n]));
        float AL = Adn;
        #pragma unroll
        for (int t = 0; t < 7; t++) AL *= AL;          // Ad^128
        #pragma unroll
        for (int rep = 0; rep < 2; rep++) {
            const int cc = cc0 + rep * 16;
            if (cc < c) {
                int e = c - 1 - cc;
                float wgt = 1.f, base = AL;
                while (e) { if (e & 1) wgt *= base; base *= base; e >>= 1; }
                part[cc * 16 + n] = wgt * g_carry[(b * NC + cc) * N + n];
            }
        }
    }
    __syncthreads();
    if (warp == 0 && lane < 16) {
        float h = 0.f;
        for (int cc = 0; cc < c; cc++) h += part[cc * 16 + lane];
        hin_s[lane] = h;
    }
    __syncthreads();

    const float hin = hin_s[lane & 15];
    const float Ad  = expf(-DTF * fabsf(A[lane & 15]));
    const float Ad2 = Ad * Ad;
    const float Ad4 = Ad2 * Ad2;
    float Ad16 = Ad4 * Ad4;  Ad16 *= Ad16;             // Ad^16
    float f = Ad;
    for (int w = 0; w < warp; w++) f *= Ad16;          // Ad^(warp*16+1)

    const size_t rowBase = (size_t)(b * S) + c * L + warp * 16;
    const ulonglong2* xw = reinterpret_cast<const ulonglong2*>(x + rowBase * D);
    const float* pw = g_p + rowBase * N;
    ull* hw = hsp + (size_t)warp * 16 * N;             // this warp's 16 rows

    #pragma unroll 1
    for (int q = 0; q < 4; q++) {
        // ---- h for 4 rows, splatted into smem ----
        {
            float pv[4];
            #pragma unroll
            for (int r = 0; r < 4; r++) pv[r] = pw[(q * 4 + r) * 16 + (lane & 15)];
            if (lane < 16) {
                float fr = f;
                #pragma unroll
                for (int r = 0; r < 4; r++) {
                    const float hn = clip10(fmaf(fr, hin, pv[r]));
                    hw[(q * 4 + r) * 16 + lane] = splat2(hn);
                    fr *= Ad;
                }
            }
            f *= Ad4;
        }

        // ---- y init: u * Dv, staged in 2-row batches ----
        ull y[4][4];
        {
            const ulonglong2 dv0 = dvs4[lane];
            const ulonglong2 dv1 = dvs4[32 + lane];
            #pragma unroll
            for (int rb = 0; rb < 2; rb++) {
                ulonglong2 xa[2], xb[2];
                const size_t base = (size_t)(q * 4 + rb * 2) * 64;
                xa[0] = xw[base + lane];        xa[1] = xw[base + 32 + lane];
                xb[0] = xw[base + 64 + lane];   xb[1] = xw[base + 96 + lane];
                y[rb * 2][0]     = mul2(xa[0].x, dv0.x);
                y[rb * 2][1]     = mul2(xa[0].y, dv0.y);
                y[rb * 2][2]     = mul2(xa[1].x, dv1.x);
                y[rb * 2][3]     = mul2(xa[1].y, dv1.y);
                y[rb * 2 + 1][0] = mul2(xb[0].x, dv0.x);
                y[rb * 2 + 1][1] = mul2(xb[0].y, dv0.y);
                y[rb * 2 + 1][2] = mul2(xb[1].x, dv1.x);
                y[rb * 2 + 1][3] = mul2(xb[1].y, dv1.y);
            }
        }
        __syncwarp();

        // ---- GEMM: n-pairs; cv via LDS.128, h-pair via uniform LDS.128 ----
        const ulonglong2* hrow2 = reinterpret_cast<const ulonglong2*>(hw + q * 4 * 16);
        #pragma unroll
        for (int np = 0; np < 8; np++) {
            const ulonglong2 cv0a = cm4s[lane * 17 + 2 * np];
            const ulonglong2 cv0b = cm4s[lane * 17 + 2 * np + 1];
            const ulonglong2 cv1a = cm4s[(32 + lane) * 17 + 2 * np];
            const ulonglong2 cv1b = cm4s[(32 + lane) * 17 + 2 * np + 1];
            #pragma unroll
            for (int r = 0; r < 4; r++) {
                const ulonglong2 hp = hrow2[r * 8 + np];  // uniform
                fma2(y[r][0], hp.x, cv0a.x);
                fma2(y[r][1], hp.x, cv0a.y);
                fma2(y[r][2], hp.x, cv1a.x);
                fma2(y[r][3], hp.x, cv1a.y);
                fma2(y[r][0], hp.y, cv0b.x);
                fma2(y[r][1], hp.y, cv0b.y);
                fma2(y[r][2], hp.y, cv1b.x);
                fma2(y[r][3], hp.y, cv1b.y);
            }
        }

        // ---- LayerNorm stats ----
        float s[4], ss[4];
        #pragma unroll
        for (int r = 0; r < 4; r++) {
            s[r] = fold2(add2(add2(y[r][0], y[r][1]), add2(y[r][2], y[r][3])));
            ull qacc = 0ull;
            #pragma unroll
            for (int k = 0; k < 4; k++) fma2(qacc, y[r][k], y[r][k]);
            ss[r] = fold2(qacc);
        }
        #pragma unroll
        for (int off = 16; off >= 1; off >>= 1) {
            #pragma unroll
            for (int r = 0; r < 4; r++) {
                s[r]  += __shfl_xor_sync(0xffffffffu, s[r], off);
                ss[r] += __shfl_xor_sync(0xffffffffu, ss[r], off);
            }
        }

        // ---- Normalize + store ----
        #pragma unroll
        for (int r = 0; r < 4; r++) {
            const float mu = s[r] * (1.0f / 256.0f);
            const float rv = rsqrtf(fmaf(ss[r], 1.0f / 256.0f, -mu * mu) + LN_EPS);
            const ull rp = splat2(rv), mp = splat2(-mu * rv);

            ulonglong2* o = reinterpret_cast<ulonglong2*>(out + (rowBase + q * 4 + r) * D);
            ulonglong2 w0, w1;
            {
                const ulonglong2 g0 = gs4[lane], b0 = bs4[lane];
                w0.x = fma2g(fma2g(y[r][0], rp, mp), g0.x, b0.x);
                w0.y = fma2g(fma2g(y[r][1], rp, mp), g0.y, b0.y);
            }
            {
                const ulonglong2 g1 = gs4[32 + lane], b1 = bs4[32 + lane];
                w1.x = fma2g(fma2g(y[r][2], rp, mp), g1.x, b1.x);
                w1.y = fma2g(fma2g(y[r][3], rp, mp), g1.y, b1.y);
            }
            o[lane]      = w0;
            o[32 + lane] = w1;
        }
    }
}

extern "C" void kernel_launch(void* const* d_in, const int* in_sizes, int n_in,
                              void* d_out, int out_size) {
    const float* x     = (const float*)d_in[0];
    const float* A     = (const float*)d_in[1];
    const float* Bm    = (const float*)d_in[2];
    const float* Cm    = (const float*)d_in[3];
    const float* Dv    = (const float*)d_in[4];
    const float* gamma = (const float*)d_in[5];
    const float* beta  = (const float*)d_in[6];
    float* out = (float*)d_out;

    kA<<<dim3(NC, Bb), 256>>>(x, A, Bm);
    kC<<<dim3(NC, Bb), 256>>>(x, A, Cm, Dv, gamma, beta, out);
}